// round 11
// baseline (speedup 1.0000x reference)
#include <cuda_runtime.h>
#include <cuda_bf16.h>

// Problem constants
#define B_   8
#define T_   4096
#define E_   1024
#define H_   16
#define L_   64
#define HD_  64
#define NBLK (T_ / L_)        // 64 blocks per sequence
#define M_   (B_ * T_)        // 32768 rows
#define N1_  (3 * E_)         // 3072

// Scratch (static device allocations are allowed; cudaMalloc is not)
__device__ float g_qkv[(size_t)M_ * N1_];   // 402 MB: qkv projection output
__device__ float g_att[(size_t)M_ * E_];    // 134 MB: attention output

// ---------------------------------------------------------------------------
// SGEMM: C[M,N] = A[M,K] @ B[N,K]^T + bias[N]
// A row-major (K contiguous), B row-major (K contiguous) -> A*B^T
// 128x128 tile, BK=16, 256 threads, 8x8 microtile per thread.
// ---------------------------------------------------------------------------
__global__ __launch_bounds__(256, 2)
void sgemm_abt(const float* __restrict__ A, const float* __restrict__ Bm,
               const float* __restrict__ bias, float* __restrict__ C,
               int M, int N, int K)
{
    constexpr int BM = 128, BN = 128, BK = 16;
    __shared__ float As[BK][BM];
    __shared__ float Bs[BK][BN];

    const int tid = threadIdx.x;
    const int tx  = tid & 15;        // 0..15  (N direction)
    const int ty  = tid >> 4;        // 0..15  (M direction)

    const long mBase = (long)blockIdx.y * BM;
    const long nBase = (long)blockIdx.x * BN;

    const float* Ag = A  + mBase * K;
    const float* Bg = Bm + nBase * K;

    float acc[8][8];
#pragma unroll
    for (int i = 0; i < 8; i++)
#pragma unroll
        for (int j = 0; j < 8; j++) acc[i][j] = 0.0f;

    for (int k0 = 0; k0 < K; k0 += BK) {
        // Load 128x16 of A and B into smem (transposed to k-major).
        // 2048 floats each / 256 threads = 2 float4 per thread per matrix.
#pragma unroll
        for (int i = 0; i < 2; i++) {
            int idx = tid + i * 256;
            int row = idx >> 2;            // 0..127
            int kc  = (idx & 3) * 4;       // 0,4,8,12
            float4 a = *(const float4*)(Ag + (long)row * K + k0 + kc);
            As[kc + 0][row] = a.x; As[kc + 1][row] = a.y;
            As[kc + 2][row] = a.z; As[kc + 3][row] = a.w;
            float4 b = *(const float4*)(Bg + (long)row * K + k0 + kc);
            Bs[kc + 0][row] = b.x; Bs[kc + 1][row] = b.y;
            Bs[kc + 2][row] = b.z; Bs[kc + 3][row] = b.w;
        }
        __syncthreads();

#pragma unroll
        for (int kk = 0; kk < BK; kk++) {
            float4 a0 = *(const float4*)&As[kk][ty * 8];
            float4 a1 = *(const float4*)&As[kk][ty * 8 + 4];
            float4 b0 = *(const float4*)&Bs[kk][tx * 8];
            float4 b1 = *(const float4*)&Bs[kk][tx * 8 + 4];
            float a[8] = {a0.x, a0.y, a0.z, a0.w, a1.x, a1.y, a1.z, a1.w};
            float b[8] = {b0.x, b0.y, b0.z, b0.w, b1.x, b1.y, b1.z, b1.w};
#pragma unroll
            for (int i = 0; i < 8; i++)
#pragma unroll
                for (int j = 0; j < 8; j++)
                    acc[i][j] += a[i] * b[j];
        }
        __syncthreads();
    }

    // Epilogue: add bias, vectorized stores.
    float bfrag[8];
#pragma unroll
    for (int j = 0; j < 8; j++) bfrag[j] = bias[nBase + tx * 8 + j];

#pragma unroll
    for (int i = 0; i < 8; i++) {
        long m = mBase + ty * 8 + i;
        float* Cp = C + m * (long)N + nBase + tx * 8;
        float4 o0, o1;
        o0.x = acc[i][0] + bfrag[0]; o0.y = acc[i][1] + bfrag[1];
        o0.z = acc[i][2] + bfrag[2]; o0.w = acc[i][3] + bfrag[3];
        o1.x = acc[i][4] + bfrag[4]; o1.y = acc[i][5] + bfrag[5];
        o1.z = acc[i][6] + bfrag[6]; o1.w = acc[i][7] + bfrag[7];
        *(float4*)(Cp)     = o0;
        *(float4*)(Cp + 4) = o1;
    }
}

// ---------------------------------------------------------------------------
// Local block attention: one CTA per (b, h, n) block of 64 tokens.
// qkv buffer layout: [b*T + t][3E], q at +0, k at +E, v at +2E, head h at
// column h*HD. Computes softmax(scale * q @ k^T) @ v into g_att[(b*T+t)][E].
//
// SMEM (static, 33.3 KB): bufA = q (padded pitch 65) -> S -> P
//                         bufB = k^T (kt[d][l])      -> v (natural [m][d])
// Thread mapping for matmuls: l = tid/4 (row), columns (tid%4)*16 .. +15.
// ---------------------------------------------------------------------------
__global__ __launch_bounds__(256)
void local_attn(const float* __restrict__ qkv, float* __restrict__ out)
{
    __shared__ float bufA[L_][HD_ + 1];   // q / S / P, pitch 65 (conflict-free)
    __shared__ float bufB[L_][HD_ + 1];   // k^T, then v

    const int bid = blockIdx.x;
    const int n = bid % NBLK;
    const int h = (bid / NBLK) % H_;
    const int b = bid / (NBLK * H_);
    const int tid = threadIdx.x;

    const long rowBase = (long)b * T_ + (long)n * L_;
    const int l  = tid >> 2;             // 0..63
    const int c0 = (tid & 3) * 16;       // 0,16,32,48
    const float scale = 0.125f;          // HD^-0.5

    const float* qp = qkv + (rowBase + l) * (long)N1_ + h * HD_;

    // Load q (scaled) into bufA[l][d]; load k transposed into bufB[d][l].
#pragma unroll
    for (int j = 0; j < 16; j += 4) {
        float4 q4 = *(const float4*)(qp + c0 + j);
        bufA[l][c0 + j + 0] = q4.x * scale;
        bufA[l][c0 + j + 1] = q4.y * scale;
        bufA[l][c0 + j + 2] = q4.z * scale;
        bufA[l][c0 + j + 3] = q4.w * scale;
        float4 k4 = *(const float4*)(qp + E_ + c0 + j);
        bufB[c0 + j + 0][l] = k4.x;
        bufB[c0 + j + 1][l] = k4.y;
        bufB[c0 + j + 2][l] = k4.z;
        bufB[c0 + j + 3][l] = k4.w;
    }
    __syncthreads();

    // S[l][m] = sum_d q[l][d] * k[m][d], m = c0..c0+15, kept in registers.
    float s[16];
#pragma unroll
    for (int j = 0; j < 16; j++) s[j] = 0.0f;
    for (int d = 0; d < HD_; d++) {
        float qv = bufA[l][d];
#pragma unroll
        for (int j = 0; j < 16; j++)
            s[j] += qv * bufB[d][c0 + j];
    }
    __syncthreads();   // all reads of q (bufA) and k^T (bufB) complete

    // Write S into bufA; load v into bufB (natural [m][d] layout).
#pragma unroll
    for (int j = 0; j < 16; j++) bufA[l][c0 + j] = s[j];
#pragma unroll
    for (int j = 0; j < 16; j += 4) {
        float4 v4 = *(const float4*)(qp + 2 * E_ + c0 + j);
        bufB[l][c0 + j + 0] = v4.x;
        bufB[l][c0 + j + 1] = v4.y;
        bufB[l][c0 + j + 2] = v4.z;
        bufB[l][c0 + j + 3] = v4.w;
    }
    __syncthreads();

    // Row softmax: warp w handles rows w*8 .. w*8+7, lane covers 2 columns.
    const int wid = tid >> 5, lane = tid & 31;
#pragma unroll
    for (int rr = 0; rr < 8; rr++) {
        int r = wid * 8 + rr;
        float v0 = bufA[r][lane];
        float v1 = bufA[r][lane + 32];
        float mx = fmaxf(v0, v1);
#pragma unroll
        for (int o = 16; o > 0; o >>= 1)
            mx = fmaxf(mx, __shfl_xor_sync(0xffffffffu, mx, o));
        float e0 = __expf(v0 - mx);
        float e1 = __expf(v1 - mx);
        float sm = e0 + e1;
#pragma unroll
        for (int o = 16; o > 0; o >>= 1)
            sm += __shfl_xor_sync(0xffffffffu, sm, o);
        float inv = 1.0f / sm;
        bufA[r][lane]      = e0 * inv;
        bufA[r][lane + 32] = e1 * inv;
    }
    __syncthreads();

    // O[l][d] = sum_m P[l][m] * v[m][d], d = c0..c0+15.
    float o[16];
#pragma unroll
    for (int j = 0; j < 16; j++) o[j] = 0.0f;
    for (int m = 0; m < L_; m++) {
        float p = bufA[l][m];
#pragma unroll
        for (int j = 0; j < 16; j++)
            o[j] += p * bufB[m][c0 + j];
    }

    float* op = out + (rowBase + l) * (long)E_ + h * HD_ + c0;
#pragma unroll
    for (int j = 0; j < 16; j += 4) {
        float4 o4 = make_float4(o[j], o[j + 1], o[j + 2], o[j + 3]);
        *(float4*)(op + j) = o4;
    }
}

// ---------------------------------------------------------------------------
// Launch: QKV GEMM -> local attention -> output GEMM (default stream, serial)
// ---------------------------------------------------------------------------
extern "C" void kernel_launch(void* const* d_in, const int* in_sizes, int n_in,
                              void* d_out, int out_size)
{
    const float* x     = (const float*)d_in[0];   // (B,T,E)
    const float* Wqkv  = (const float*)d_in[1];   // (3E,E)
    const float* bqkv  = (const float*)d_in[2];   // (3E,)
    const float* Wout  = (const float*)d_in[3];   // (E,E)
    const float* bout  = (const float*)d_in[4];   // (E,)
    float* out = (float*)d_out;                   // (B,T,E)

    void* p;
    cudaGetSymbolAddress(&p, g_qkv);
    float* qkv = (float*)p;
    cudaGetSymbolAddress(&p, g_att);
    float* att = (float*)p;

    // GEMM1: qkv = x @ Wqkv^T + bqkv   (32768 x 3072 x 1024)
    sgemm_abt<<<dim3(N1_ / 128, M_ / 128), 256>>>(x, Wqkv, bqkv, qkv,
                                                  M_, N1_, E_);
    // Local block attention (8 * 16 * 64 = 8192 blocks)
    local_attn<<<B_ * H_ * NBLK, 256>>>(qkv, att);

    // GEMM2: out = att @ Wout^T + bout (32768 x 1024 x 1024)
    sgemm_abt<<<dim3(E_ / 128, M_ / 128), 256>>>(att, Wout, bout, out,
                                                 M_, E_, E_);
}

// round 13
// speedup vs baseline: 2.2161x; 2.2161x over previous
#include <cuda_runtime.h>
#include <cuda_bf16.h>
#include <cstdint>

// Problem constants
#define B_   8
#define T_   4096
#define E_   1024
#define H_   16
#define L_   64
#define HD_  64
#define NBLK (T_ / L_)        // 64 blocks per sequence
#define M_   (B_ * T_)        // 32768 rows
#define N1_  (3 * E_)         // 3072

// Scratch (static device arrays: allowed; cudaMalloc is not)
__device__ float g_qkv[(size_t)M_ * N1_];   // 402 MB
__device__ float g_att[(size_t)M_ * E_];    // 134 MB

// ---------------------------------------------------------------------------
// Helpers
// ---------------------------------------------------------------------------
__device__ __forceinline__ uint32_t smem_u32(const void* p) {
    uint32_t a;
    asm("{ .reg .u64 t; cvta.to.shared.u64 t, %1; cvt.u32.u64 %0, t; }"
        : "=r"(a) : "l"(p));
    return a;
}

__device__ __forceinline__ void ldsm4(uint32_t* r, uint32_t addr) {
    asm volatile("ldmatrix.sync.aligned.m8n8.x4.shared.b16 {%0,%1,%2,%3}, [%4];"
                 : "=r"(r[0]), "=r"(r[1]), "=r"(r[2]), "=r"(r[3])
                 : "r"(addr));
}

__device__ __forceinline__ void mma16816(float* c, const uint32_t* a,
                                         const uint32_t* b) {
    asm volatile(
        "mma.sync.aligned.m16n8k16.row.col.f32.bf16.bf16.f32 "
        "{%0,%1,%2,%3}, {%4,%5,%6,%7}, {%8,%9}, {%0,%1,%2,%3};"
        : "+f"(c[0]), "+f"(c[1]), "+f"(c[2]), "+f"(c[3])
        : "r"(a[0]), "r"(a[1]), "r"(a[2]), "r"(a[3]),
          "r"(b[0]), "r"(b[1]));
}

// Split a float4 (4 consecutive k) into bf16 hi/lo and store 8B to each buf.
__device__ __forceinline__ void split_store(char* hiBase, char* loBase,
                                            uint32_t off, float4 v) {
    __nv_bfloat162 h0 = __floats2bfloat162_rn(v.x, v.y);
    __nv_bfloat162 h1 = __floats2bfloat162_rn(v.z, v.w);
    float2 f0 = __bfloat1622float2(h0);
    float2 f1 = __bfloat1622float2(h1);
    __nv_bfloat162 l0 = __floats2bfloat162_rn(v.x - f0.x, v.y - f0.y);
    __nv_bfloat162 l1 = __floats2bfloat162_rn(v.z - f1.x, v.w - f1.y);
    uint2 hw, lw;
    hw.x = *reinterpret_cast<uint32_t*>(&h0);
    hw.y = *reinterpret_cast<uint32_t*>(&h1);
    lw.x = *reinterpret_cast<uint32_t*>(&l0);
    lw.y = *reinterpret_cast<uint32_t*>(&l1);
    *reinterpret_cast<uint2*>(hiBase + off) = hw;
    *reinterpret_cast<uint2*>(loBase + off) = lw;
}

// ---------------------------------------------------------------------------
// Split-bf16 tensor-core GEMM: C[M,N] = A[M,K] @ B[N,K]^T + bias[N]
// CTA tile 128x128, BK=32, 256 threads (8 warps, 4M x 2N).
// smem per stage: Ahi|Alo|Bhi|Blo, each 128 rows x 40 bf16 (pitch 80B) = 10240B
// Double-buffered: 2 x 40960 = 81920 B dynamic smem.
// ---------------------------------------------------------------------------
#define GBM 128
#define GBN 128
#define GBK 32
#define PITCH 80                     // bytes per smem row (40 bf16)
#define SEG  10240                   // bytes per sub-buffer (128 * 80)
#define STAGE (4 * SEG)              // 40960
#define GEMM_SMEM (2 * STAGE)        // 81920

__global__ __launch_bounds__(256, 1)
void gemm_tc(const float* __restrict__ A, const float* __restrict__ Bm,
             const float* __restrict__ bias, float* __restrict__ C,
             int N, int K)
{
    extern __shared__ char smem[];

    const int tid  = threadIdx.x;
    const int wid  = tid >> 5;
    const int lane = tid & 31;
    const int wm   = wid & 3;          // warp row (4)
    const int wn   = wid >> 2;         // warp col (2)

    const long mBase = (long)blockIdx.y * GBM;
    const long nBase = (long)blockIdx.x * GBN;
    const float* Ag = A  + mBase * K;
    const float* Bg = Bm + nBase * K;

    // gmem load assignment: 128 rows x 32 floats = 1024 float4, 4 per thread
    const int gRow[1] = {0};
    (void)gRow;

    float acc[2][8][4];
#pragma unroll
    for (int mt = 0; mt < 2; mt++)
#pragma unroll
        for (int nt = 0; nt < 8; nt++)
#pragma unroll
            for (int i = 0; i < 4; i++) acc[mt][nt][i] = 0.0f;

    // ldmatrix base addresses (within a stage), lane-resolved
    // A x4 quads: [r0-7 klo, r8-15 klo, r0-7 khi, r8-15 khi]
    const uint32_t aRow  = (((lane >> 3) & 1) * 8) + (lane & 7);
    const uint32_t aKoff = (lane >> 4) * 16;
    // B x4 quads: [n0-7 klo, n0-7 khi, n8-15 klo, n8-15 khi]
    const uint32_t bRow  = ((lane >> 4) * 8) + (lane & 7);
    const uint32_t bKoff = ((lane >> 3) & 1) * 16;

    const uint32_t smemBase = smem_u32(smem);

    float4 aReg[4], bReg[4];
    const int NC = K / GBK;

    // Prologue: load chunk 0
#pragma unroll
    for (int i = 0; i < 4; i++) {
        int idx = tid + i * 256;
        int row = idx >> 3, kc = (idx & 7) * 4;
        aReg[i] = *(const float4*)(Ag + (long)row * K + kc);
        bReg[i] = *(const float4*)(Bg + (long)row * K + kc);
    }
#pragma unroll
    for (int i = 0; i < 4; i++) {
        int idx = tid + i * 256;
        int row = idx >> 3, kc = (idx & 7) * 4;
        uint32_t off = row * PITCH + kc * 2;
        split_store(smem,           smem + SEG,     off, aReg[i]);
        split_store(smem + 2 * SEG, smem + 3 * SEG, off, bReg[i]);
    }
    __syncthreads();

    for (int c = 0; c < NC; c++) {
        const int p = c & 1;
        const int kNext = (c + 1) * GBK;

        // Issue gmem loads for next chunk (hidden under MMAs)
        if (c + 1 < NC) {
#pragma unroll
            for (int i = 0; i < 4; i++) {
                int idx = tid + i * 256;
                int row = idx >> 3, kc = (idx & 7) * 4;
                aReg[i] = *(const float4*)(Ag + (long)row * K + kNext + kc);
                bReg[i] = *(const float4*)(Bg + (long)row * K + kNext + kc);
            }
        }

        // Compute on stage p
        const uint32_t stage = smemBase + p * STAGE;
        const uint32_t aHiB = stage           + (wm * 32 + aRow) * PITCH + aKoff;
        const uint32_t aLoB = stage + SEG     + (wm * 32 + aRow) * PITCH + aKoff;
        const uint32_t bHiB = stage + 2 * SEG + (wn * 64 + bRow) * PITCH + bKoff;
        const uint32_t bLoB = stage + 3 * SEG + (wn * 64 + bRow) * PITCH + bKoff;

#pragma unroll
        for (int ks = 0; ks < 2; ks++) {
            uint32_t ahi[2][4], alo[2][4], bhi[4][4], blo[4][4];
#pragma unroll
            for (int mt = 0; mt < 2; mt++) {
                ldsm4(ahi[mt], aHiB + mt * 16 * PITCH + ks * 32);
                ldsm4(alo[mt], aLoB + mt * 16 * PITCH + ks * 32);
            }
#pragma unroll
            for (int np = 0; np < 4; np++) {
                ldsm4(bhi[np], bHiB + np * 16 * PITCH + ks * 32);
                ldsm4(blo[np], bLoB + np * 16 * PITCH + ks * 32);
            }
#pragma unroll
            for (int mt = 0; mt < 2; mt++)
#pragma unroll
                for (int nt = 0; nt < 8; nt++) {
                    const uint32_t* bh = &bhi[nt >> 1][(nt & 1) * 2];
                    const uint32_t* bl = &blo[nt >> 1][(nt & 1) * 2];
                    mma16816(acc[mt][nt], ahi[mt], bh);   // hi*hi
                    mma16816(acc[mt][nt], ahi[mt], bl);   // hi*lo
                    mma16816(acc[mt][nt], alo[mt], bh);   // lo*hi
                }
        }

        // Store next chunk into the other stage
        if (c + 1 < NC) {
            char* nb = smem + ((c + 1) & 1) * STAGE;
#pragma unroll
            for (int i = 0; i < 4; i++) {
                int idx = tid + i * 256;
                int row = idx >> 3, kc = (idx & 7) * 4;
                uint32_t off = row * PITCH + kc * 2;
                split_store(nb,           nb + SEG,     off, aReg[i]);
                split_store(nb + 2 * SEG, nb + 3 * SEG, off, bReg[i]);
            }
            __syncthreads();
        }
    }

    // Epilogue: acc + bias -> C (standard m16n8 fragment layout)
    const int g   = lane >> 2;         // row group 0..7
    const int tg  = lane & 3;          // col pair 0..3
    const long wRow = mBase + wm * 32 + g;
    const long wCol = nBase + wn * 64 + tg * 2;

    float2 bfrag[8];
#pragma unroll
    for (int nt = 0; nt < 8; nt++)
        bfrag[nt] = *(const float2*)(bias + wCol + nt * 8);

#pragma unroll
    for (int mt = 0; mt < 2; mt++) {
        long r0 = wRow + mt * 16;
#pragma unroll
        for (int nt = 0; nt < 8; nt++) {
            float2 o0, o1;
            o0.x = acc[mt][nt][0] + bfrag[nt].x;
            o0.y = acc[mt][nt][1] + bfrag[nt].y;
            o1.x = acc[mt][nt][2] + bfrag[nt].x;
            o1.y = acc[mt][nt][3] + bfrag[nt].y;
            *(float2*)(C + r0 * N + wCol + nt * 8)       = o0;
            *(float2*)(C + (r0 + 8) * N + wCol + nt * 8) = o1;
        }
    }
}

// ---------------------------------------------------------------------------
// Local block attention (unchanged — fp32, smem, warp softmax)
// ---------------------------------------------------------------------------
__global__ __launch_bounds__(256)
void local_attn(const float* __restrict__ qkv, float* __restrict__ out)
{
    __shared__ float bufA[L_][HD_ + 1];
    __shared__ float bufB[L_][HD_ + 1];

    const int bid = blockIdx.x;
    const int n = bid % NBLK;
    const int h = (bid / NBLK) % H_;
    const int b = bid / (NBLK * H_);
    const int tid = threadIdx.x;

    const long rowBase = (long)b * T_ + (long)n * L_;
    const int l  = tid >> 2;
    const int c0 = (tid & 3) * 16;
    const float scale = 0.125f;

    const float* qp = qkv + (rowBase + l) * (long)N1_ + h * HD_;

#pragma unroll
    for (int j = 0; j < 16; j += 4) {
        float4 q4 = *(const float4*)(qp + c0 + j);
        bufA[l][c0 + j + 0] = q4.x * scale;
        bufA[l][c0 + j + 1] = q4.y * scale;
        bufA[l][c0 + j + 2] = q4.z * scale;
        bufA[l][c0 + j + 3] = q4.w * scale;
        float4 k4 = *(const float4*)(qp + E_ + c0 + j);
        bufB[c0 + j + 0][l] = k4.x;
        bufB[c0 + j + 1][l] = k4.y;
        bufB[c0 + j + 2][l] = k4.z;
        bufB[c0 + j + 3][l] = k4.w;
    }
    __syncthreads();

    float s[16];
#pragma unroll
    for (int j = 0; j < 16; j++) s[j] = 0.0f;
    for (int d = 0; d < HD_; d++) {
        float qv = bufA[l][d];
#pragma unroll
        for (int j = 0; j < 16; j++)
            s[j] += qv * bufB[d][c0 + j];
    }
    __syncthreads();

#pragma unroll
    for (int j = 0; j < 16; j++) bufA[l][c0 + j] = s[j];
#pragma unroll
    for (int j = 0; j < 16; j += 4) {
        float4 v4 = *(const float4*)(qp + 2 * E_ + c0 + j);
        bufB[l][c0 + j + 0] = v4.x;
        bufB[l][c0 + j + 1] = v4.y;
        bufB[l][c0 + j + 2] = v4.z;
        bufB[l][c0 + j + 3] = v4.w;
    }
    __syncthreads();

    const int wid = tid >> 5, lane = tid & 31;
#pragma unroll
    for (int rr = 0; rr < 8; rr++) {
        int r = wid * 8 + rr;
        float v0 = bufA[r][lane];
        float v1 = bufA[r][lane + 32];
        float mx = fmaxf(v0, v1);
#pragma unroll
        for (int o = 16; o > 0; o >>= 1)
            mx = fmaxf(mx, __shfl_xor_sync(0xffffffffu, mx, o));
        float e0 = __expf(v0 - mx);
        float e1 = __expf(v1 - mx);
        float sm = e0 + e1;
#pragma unroll
        for (int o = 16; o > 0; o >>= 1)
            sm += __shfl_xor_sync(0xffffffffu, sm, o);
        float inv = 1.0f / sm;
        bufA[r][lane]      = e0 * inv;
        bufA[r][lane + 32] = e1 * inv;
    }
    __syncthreads();

    float o[16];
#pragma unroll
    for (int j = 0; j < 16; j++) o[j] = 0.0f;
    for (int m = 0; m < L_; m++) {
        float p = bufA[l][m];
#pragma unroll
        for (int j = 0; j < 16; j++)
            o[j] += p * bufB[m][c0 + j];
    }

    float* op = out + (rowBase + l) * (long)E_ + h * HD_ + c0;
#pragma unroll
    for (int j = 0; j < 16; j += 4) {
        float4 o4 = make_float4(o[j], o[j + 1], o[j + 2], o[j + 3]);
        *(float4*)(op + j) = o4;
    }
}

// ---------------------------------------------------------------------------
// Launch
// ---------------------------------------------------------------------------
extern "C" void kernel_launch(void* const* d_in, const int* in_sizes, int n_in,
                              void* d_out, int out_size)
{
    const float* x    = (const float*)d_in[0];
    const float* Wqkv = (const float*)d_in[1];
    const float* bqkv = (const float*)d_in[2];
    const float* Wout = (const float*)d_in[3];
    const float* bout = (const float*)d_in[4];
    float* out = (float*)d_out;

    void* p;
    cudaGetSymbolAddress(&p, g_qkv);
    float* qkv = (float*)p;
    cudaGetSymbolAddress(&p, g_att);
    float* att = (float*)p;

    cudaFuncSetAttribute(gemm_tc, cudaFuncAttributeMaxDynamicSharedMemorySize,
                         GEMM_SMEM);

    // GEMM1: qkv = x @ Wqkv^T + bqkv  (32768 x 3072 x 1024)
    gemm_tc<<<dim3(N1_ / GBN, M_ / GBM), 256, GEMM_SMEM>>>(x, Wqkv, bqkv, qkv,
                                                           N1_, E_);
    // Local block attention
    local_attn<<<B_ * H_ * NBLK, 256>>>(qkv, att);

    // GEMM2: out = att @ Wout^T + bout (32768 x 1024 x 1024)
    gemm_tc<<<dim3(E_ / GBN, M_ / GBM), 256, GEMM_SMEM>>>(att, Wout, bout, out,
                                                          E_, E_);
}